// round 12
// baseline (speedup 1.0000x reference)
#include <cuda_runtime.h>

// Soft-DTW, gamma = 0.01, p = 2, B = 64, M = N = 512.
// Cluster of 2 CTAs per batch (grid 128, cluster_dims(2,1,1)).
// CTA rank r owns columns [256r, 256r+256); 128 threads, thread jjl owns
// colA = 256r + 2*jjl, colB = colA + 1. 4 warps/CTA = 1 warp per SMSP:
// halves the per-SMSP MUFU pressure vs the 8-warp single-CTA version.
// Global warp index W = 4r + w; warp W handles global steps s = t + 64W,
// local t in [0, 575); cell A = (iiA = t - 2*lane, colA), B = (iiA-1, colB).
//   B deps all-register; A deps via shfl (lane>0) / mailbox (lane 0).
// Mailboxes (write-once, 512 slots of {value, tag=row}, single 64-bit store):
//   warp w<3 publishes into local bnd[w], consumed by local warp w+1.
//   CTA0.w3 publishes into CTA1's bnd[3] via mapa + st.shared::cluster.b64.
//   CTA1.w0 consumes local bnd[3] (inbox). CTA0.w0 consumes bnd[3] prefilled
//   as an always-valid dummy (left border = BIG). CTA1.w3 publishes nothing.

#define BIG   1e30f
#define KEXP  144.26950408889634f    // 100 * log2(e)
#define GLN2  0.006931471805599453f  // 0.01 * ln(2)

__device__ __forceinline__ float ex2f_(float v) {
    float r; asm("ex2.approx.ftz.f32 %0, %1;" : "=f"(r) : "f"(v)); return r;
}
__device__ __forceinline__ float lg2f_(float v) {
    float r; asm("lg2.approx.ftz.f32 %0, %1;" : "=f"(r) : "f"(v)); return r;
}

// softmin3 = m - gamma*ln(1 + e^{(m-v1)/g} + e^{(m-v2)/g})  (proven numerics)
__device__ __forceinline__ float softmin3(float dg, float up, float lf) {
    float t1 = fminf(dg, up);
    float t2 = fmaxf(dg, up);
    float m  = fminf(t1, lf);
    float u  = fmaxf(t1, lf);
    float mk = m * KEXP;
    float a1 = fmaf(-KEXP, t2, mk);
    float a2 = fmaf(-KEXP, u,  mk);
    float ss = 1.0f + ex2f_(a1) + ex2f_(a2);
    return fmaf(-GLN2, lg2f_(ss), m);
}

__device__ __forceinline__ uint2 lds_v2_vol(const uint2* p) {
    uint2 r; unsigned a = (unsigned)__cvta_generic_to_shared(p);
    asm volatile("ld.volatile.shared.v2.u32 {%0,%1}, [%2];"
                 : "=r"(r.x), "=r"(r.y) : "r"(a));
    return r;
}
__device__ __forceinline__ void sts_v2_vol(uint2* p, unsigned vx, unsigned vy) {
    unsigned a = (unsigned)__cvta_generic_to_shared(p);
    asm volatile("st.volatile.shared.v2.u32 [%0], {%1,%2};"
                 :: "r"(a), "r"(vx), "r"(vy) : "memory");
}
// Remote (DSMEM) publish: single 64-bit store -> {value,tag} indivisible.
__device__ __forceinline__ void sts_cluster_b64(unsigned raddr, unsigned vx, unsigned vy) {
    unsigned long long pk = ((unsigned long long)vy << 32) | vx;
    asm volatile("st.shared::cluster.b64 [%0], %1;" :: "r"(raddr), "l"(pk) : "memory");
}
// Verify prefetched mailbox entry {pre.x=valBits, pre.y=tag} against tag t;
// reload (rare) until the tag matches. Warp-uniform slot => uniform branches.
__device__ __forceinline__ float mb_verify(const uint2* slot, unsigned t, uint2& pre) {
    unsigned a = (unsigned)__cvta_generic_to_shared(slot);
    asm volatile("{\n\t"
        ".reg .pred p;\n\t"
        "setp.eq.u32 p, %1, %2;\n\t"
        "@p bra D%=;\n\t"
        "R%=:\n\t"
        "ld.volatile.shared.v2.u32 {%0,%1}, [%3];\n\t"
        "setp.ne.u32 p, %1, %2;\n\t"
        "@p bra R%=;\n\t"
        "D%=:\n\t"
        "}"
        : "+r"(pre.x), "+r"(pre.y) : "r"(t), "r"(a) : "memory");
    return __uint_as_float(pre.x);
}

__global__ __launch_bounds__(128, 1) __cluster_dims__(2, 1, 1)
void softdtw_kernel(const float* __restrict__ x,
                    const float* __restrict__ y,
                    float* __restrict__ out)
{
    __shared__ float yshp_raw[640];  // rows [-64, 576); offset 64; pads zeroed
    __shared__ uint2 bnd[4][512];    // [0..2]: local mailboxes; [3]: dummy/inbox

    const int b    = blockIdx.x >> 1;
    const int r    = blockIdx.x & 1;       // cluster rank
    const int jjl  = threadIdx.x;          // 0..127
    const int w    = jjl >> 5;             // local warp 0..3
    const int lane = jjl & 31;
    const int W    = 4 * r + w;            // global warp 0..7
    const int colA = 256 * r + 2 * jjl;
    const int colB = colA + 1;
    float* yshp = yshp_raw + 64;

    // y rows: every CTA needs all 512
    for (int i = jjl; i < 512; i += 128) yshp[i] = y[b * 512 + i];
    if (jjl < 64) { yshp_raw[jjl] = 0.0f; yshp_raw[576 + jjl] = 0.0f; }
    const float xA = x[b * 512 + colA];
    const float xB = x[b * 512 + colB];

    // poison local mailboxes 0..2; row 3: dummy (r=0) or poisoned inbox (r=1)
    {
        uint2* flat = &bnd[0][0];
        for (int t = jjl; t < 3 * 512; t += 128) flat[t].y = 0xFFFFFFFFu;
        if (r == 0) {
            for (int t = jjl; t < 512; t += 128)
                bnd[3][t] = make_uint2(__float_as_uint(BIG), (unsigned)t);
        } else {
            for (int t = jjl; t < 512; t += 128) bnd[3][t].y = 0xFFFFFFFFu;
        }
    }
    __syncthreads();
    // cluster barrier: CTA1's inbox poison must precede CTA0's remote writes
    asm volatile("barrier.cluster.arrive.aligned;" ::: "memory");
    asm volatile("barrier.cluster.wait.aligned;" ::: "memory");

    const uint2* mrow = bnd[(w + 3) & 3];   // w0 -> row3 (dummy/inbox), else bnd[w-1]
    uint2*       prow = bnd[w & 3];         // local producer row (w < 3)
    const bool   isPub     = (lane == 31) && (W < 7);
    const bool   pubRemote = (w == 3);      // only reachable when r == 0 (W==3)

    // remote base address of peer CTA's bnd[3] (computed once; used iff pubRemote)
    unsigned remBase = 0;
    {
        unsigned la = (unsigned)__cvta_generic_to_shared(&bnd[3][0]);
        asm("mapa.shared::cluster.u32 %0, %1, %2;" : "=r"(remBase) : "r"(la), "r"(1));
    }

    float aPrev  = BIG;                     // A(t-1)
    float aPrev2 = BIG;                     // A(t-2)
    float bPrev  = BIG;                     // B(t-1)
    float nbPrev = (r == 0 && jjl == 0) ? 0.0f : BIG;  // R[-1,-1] = 0 seed

    float yA = yshp[-2 * lane];             // ysh[iiA] at t=0 (pad if negative)
    float yB = yshp[-2 * lane - 1];         // ysh[iiA-1]

    uint2 pre = lds_v2_vol(&mrow[0]);       // prefetch slot 0

    // ---- phase A: local t = 0..511 (mailbox active) ----
    #pragma unroll 2
    for (int t = 0; t < 512; ++t) {
        const int iiA  = t - 2 * lane;
        const int rowB = iiA - 1;

        float nbCur = __shfl_up_sync(0xffffffffu, bPrev, 1);

        // B cell first: register-only deps, hides mailbox latency
        float dB = xB - yB;
        float rB = fmaf(dB, dB, softmin3(aPrev2, bPrev, aPrev));
        rB = ((unsigned)rowB < 512u) ? rB : BIG;

        // publish ASAP (lane 31, W < 7)
        if (isPub && (unsigned)rowB < 512u) {
            if (pubRemote) sts_cluster_b64(remBase + (unsigned)rowB * 8u,
                                           __float_as_uint(rB), (unsigned)rowB);
            else           sts_v2_vol(&prow[rowB], __float_as_uint(rB), (unsigned)rowB);
        }

        // mailbox value for lane 0 (uniform slot/tag across the warp)
        float mv = mb_verify(&mrow[t], (unsigned)t, pre);
        if (lane == 0) nbCur = mv;

        // A cell
        float dA = xA - yA;
        float rA = fmaf(dA, dA, softmin3(nbPrev, aPrev, nbCur));
        rA = ((unsigned)iiA < 512u) ? rA : BIG;

        // rotate state
        aPrev2 = aPrev;  aPrev = rA;  bPrev = rB;  nbPrev = nbCur;
        yB = yA;
        yA = yshp[iiA + 1];

        pre = lds_v2_vol(&mrow[min(t + 1, 511)]);   // prefetch next slot
    }

    // ---- phase B: local t = 512..574 (lane 0 inactive; no mailbox) ----
    #pragma unroll 2
    for (int t = 512; t <= 574; ++t) {
        const int iiA  = t - 2 * lane;
        const int rowB = iiA - 1;

        float nbCur = __shfl_up_sync(0xffffffffu, bPrev, 1);
        if (lane == 0) nbCur = BIG;

        float dB = xB - yB;
        float rB = fmaf(dB, dB, softmin3(aPrev2, bPrev, aPrev));
        rB = ((unsigned)rowB < 512u) ? rB : BIG;

        if (isPub && (unsigned)rowB < 512u) {
            if (pubRemote) sts_cluster_b64(remBase + (unsigned)rowB * 8u,
                                           __float_as_uint(rB), (unsigned)rowB);
            else           sts_v2_vol(&prow[rowB], __float_as_uint(rB), (unsigned)rowB);
        }

        float dA = xA - yA;
        float rA = fmaf(dA, dA, softmin3(nbPrev, aPrev, nbCur));
        rA = ((unsigned)iiA < 512u) ? rA : BIG;

        aPrev2 = aPrev;  aPrev = rA;  bPrev = rB;  nbPrev = nbCur;
        yB = yA;
        yA = yshp[iiA + 1];
    }

    // result: B cell of global col 511 (r=1, jjl=127) at t=574 -> R[511,511]
    if (r == 1 && jjl == 127) out[b] = bPrev;

    // keep the cluster alive until all DSMEM traffic is consumed
    asm volatile("barrier.cluster.arrive.aligned;" ::: "memory");
    asm volatile("barrier.cluster.wait.aligned;" ::: "memory");
}

extern "C" void kernel_launch(void* const* d_in, const int* in_sizes, int n_in,
                              void* d_out, int out_size)
{
    const float* x = (const float*)d_in[0];
    const float* y = (const float*)d_in[1];
    float* out = (float*)d_out;
    softdtw_kernel<<<128, 128>>>(x, y, out);
}

// round 13
// speedup vs baseline: 1.0456x; 1.0456x over previous
#include <cuda_runtime.h>

// Soft-DTW, gamma = 0.01, p = 2, B = 64, M = N = 512.
// 32 CTAs x 512 threads; each CTA runs TWO independent batches:
//   threads [0,256)  (warps 0-7)  -> batch 2*blockIdx
//   threads [256,512) (warps 8-15) -> batch 2*blockIdx+1
// Each half is the proven R9 pipeline: thread jj owns cols colA=2jj, colB=2jj+1;
// at local step t (global s = t + 64w) computes A=(iiA=t-2*lane,colA), B=(iiA-1,colB).
//   B deps all-register; A deps via shfl (lane>0) / write-once mailbox (lane 0).
// Two independent DP chains per SMSP fill each other's dependency-stall bubbles.

#define BIG   1e30f
#define KEXP  144.26950408889634f    // 100 * log2(e)
#define GLN2  0.006931471805599453f  // 0.01 * ln(2)

#define SMEM_BYTES (2 * (8 * 512 * 8) + 2 * (512 * 4))   // bnd[2][8][512] + ysh[2][512]

__device__ __forceinline__ float ex2f_(float v) {
    float r; asm("ex2.approx.ftz.f32 %0, %1;" : "=f"(r) : "f"(v)); return r;
}
__device__ __forceinline__ float lg2f_(float v) {
    float r; asm("lg2.approx.ftz.f32 %0, %1;" : "=f"(r) : "f"(v)); return r;
}

// softmin3 = m - gamma*ln(1 + e^{(m-v1)/g} + e^{(m-v2)/g})  (proven numerics)
__device__ __forceinline__ float softmin3(float dg, float up, float lf) {
    float t1 = fminf(dg, up);
    float t2 = fmaxf(dg, up);
    float m  = fminf(t1, lf);
    float u  = fmaxf(t1, lf);
    float mk = m * KEXP;
    float a1 = fmaf(-KEXP, t2, mk);
    float a2 = fmaf(-KEXP, u,  mk);
    float ss = 1.0f + ex2f_(a1) + ex2f_(a2);
    return fmaf(-GLN2, lg2f_(ss), m);
}

__device__ __forceinline__ uint2 lds_v2_vol(const uint2* p) {
    uint2 r; unsigned a = (unsigned)__cvta_generic_to_shared(p);
    asm volatile("ld.volatile.shared.v2.u32 {%0,%1}, [%2];"
                 : "=r"(r.x), "=r"(r.y) : "r"(a));
    return r;
}
__device__ __forceinline__ void sts_v2_vol(uint2* p, unsigned vx, unsigned vy) {
    unsigned a = (unsigned)__cvta_generic_to_shared(p);
    asm volatile("st.volatile.shared.v2.u32 [%0], {%1,%2};"
                 :: "r"(a), "r"(vx), "r"(vy) : "memory");
}
// Verify prefetched mailbox entry {pre.x=valBits, pre.y=tag} against tag t;
// reload (rare) until the tag matches. Warp-uniform slot => uniform branches.
__device__ __forceinline__ float mb_verify(const uint2* slot, unsigned t, uint2& pre) {
    unsigned a = (unsigned)__cvta_generic_to_shared(slot);
    asm volatile("{\n\t"
        ".reg .pred p;\n\t"
        "setp.eq.u32 p, %1, %2;\n\t"
        "@p bra D%=;\n\t"
        "R%=:\n\t"
        "ld.volatile.shared.v2.u32 {%0,%1}, [%3];\n\t"
        "setp.ne.u32 p, %1, %2;\n\t"
        "@p bra R%=;\n\t"
        "D%=:\n\t"
        "}"
        : "+r"(pre.x), "+r"(pre.y) : "r"(t), "r"(a) : "memory");
    return __uint_as_float(pre.x);
}

__global__ __launch_bounds__(512, 1)
void softdtw_kernel(const float* __restrict__ x,
                    const float* __restrict__ y,
                    float* __restrict__ out)
{
    extern __shared__ __align__(16) char smraw[];
    // carve: bnd[2][8][512] (uint2), then ysh[2][512] (float)
    uint2 (*bndAll)[8][512] = (uint2 (*)[8][512])smraw;
    float*  yshAll          = (float*)(smraw + 2 * 8 * 512 * sizeof(uint2));

    const int tid  = threadIdx.x;
    const int h    = tid >> 8;             // half: 0 or 1 (independent batch)
    const int jj   = tid & 255;            // 0..255 within the half
    const int b    = 2 * blockIdx.x + h;
    const int w    = jj >> 5;              // warp-within-half 0..7
    const int lane = jj & 31;
    const int colA = 2 * jj;
    const int colB = colA + 1;

    uint2 (*bnd)[512] = bndAll[h];
    float* ysh        = yshAll + h * 512;

    ysh[colA] = y[b * 512 + colA];
    ysh[colB] = y[b * 512 + colB];
    const float xA = x[b * 512 + colA];
    const float xB = x[b * 512 + colB];

    // poison tags of real mailboxes 0..6; prefill dummy row 7 with {BIG, tag=t}
    {
        uint2* flat = &bnd[0][0];
        for (int t = jj; t < 7 * 512; t += 256) flat[t].y = 0xFFFFFFFFu;
        for (int t = jj; t < 512; t += 256)
            bnd[7][t] = make_uint2(__float_as_uint(BIG), (unsigned)t);
    }
    __syncthreads();                        // the only full barrier

    const uint2* mrow = bnd[(w + 7) & 7];   // w=0 -> dummy row 7; else bnd[w-1]
    uint2*       prow = bnd[w & 7];         // producer row (used only if w<7)
    const bool   isPub = (lane == 31) && (w < 7);

    float aPrev  = BIG;                     // A(t-1)
    float aPrev2 = BIG;                     // A(t-2)
    float bPrev  = BIG;                     // B(t-1)
    float nbPrev = (jj == 0) ? 0.0f : BIG;  // neighbor B(t-2); R[-1,-1]=0 seed

    // y registers: yA = ysh[iiA], yB = ysh[iiA-1] (clamped reads; inactive lanes
    // have their results overwritten by the border selects)
    float yA = ysh[0];
    float yB = ysh[0];

    uint2 pre = lds_v2_vol(&mrow[0]);       // prefetch slot 0

    // ---- phase A: local t = 0..511 (mailbox active) ----
    #pragma unroll 2
    for (int t = 0; t < 512; ++t) {
        const int iiA  = t - 2 * lane;
        const int rowB = iiA - 1;

        float nbCur = __shfl_up_sync(0xffffffffu, bPrev, 1);

        // B cell first: register-only deps, hides mailbox latency
        float dB = xB - yB;
        float rB = fmaf(dB, dB, softmin3(aPrev2, bPrev, aPrev));
        rB = ((unsigned)rowB < 512u) ? rB : BIG;

        // publish ASAP to feed the downstream warp
        if (isPub && (unsigned)rowB < 512u)
            sts_v2_vol(&prow[rowB], __float_as_uint(rB), (unsigned)rowB);

        // mailbox value for lane 0 (uniform slot/tag across the warp)
        float mv = mb_verify(&mrow[t], (unsigned)t, pre);
        if (lane == 0) nbCur = mv;

        // A cell
        float dA = xA - yA;
        float rA = fmaf(dA, dA, softmin3(nbPrev, aPrev, nbCur));
        rA = ((unsigned)iiA < 512u) ? rA : BIG;

        // rotate state
        aPrev2 = aPrev;  aPrev = rA;  bPrev = rB;  nbPrev = nbCur;
        yB = yA;
        yA = ysh[min(max(iiA + 1, 0), 511)];

        pre = lds_v2_vol(&mrow[min(t + 1, 511)]);   // prefetch next slot
    }

    // ---- phase B: local t = 512..574 (lane 0 inactive; no mailbox) ----
    #pragma unroll 2
    for (int t = 512; t <= 574; ++t) {
        const int iiA  = t - 2 * lane;
        const int rowB = iiA - 1;

        float nbCur = __shfl_up_sync(0xffffffffu, bPrev, 1);
        if (lane == 0) nbCur = BIG;

        float dB = xB - yB;
        float rB = fmaf(dB, dB, softmin3(aPrev2, bPrev, aPrev));
        rB = ((unsigned)rowB < 512u) ? rB : BIG;

        if (isPub && (unsigned)rowB < 512u)
            sts_v2_vol(&prow[rowB], __float_as_uint(rB), (unsigned)rowB);

        float dA = xA - yA;
        float rA = fmaf(dA, dA, softmin3(nbPrev, aPrev, nbCur));
        rA = ((unsigned)iiA < 512u) ? rA : BIG;

        aPrev2 = aPrev;  aPrev = rA;  bPrev = rB;  nbPrev = nbCur;
        yB = yA;
        yA = ysh[min(max(iiA + 1, 0), 511)];
    }

    if (jj == 255) out[b] = bPrev;          // B at global step 1022 -> R[511,511]
}

extern "C" void kernel_launch(void* const* d_in, const int* in_sizes, int n_in,
                              void* d_out, int out_size)
{
    const float* x = (const float*)d_in[0];
    const float* y = (const float*)d_in[1];
    float* out = (float*)d_out;
    cudaFuncSetAttribute(softdtw_kernel,
                         cudaFuncAttributeMaxDynamicSharedMemorySize, SMEM_BYTES);
    softdtw_kernel<<<32, 512, SMEM_BYTES>>>(x, y, out);
}

// round 14
// speedup vs baseline: 1.1929x; 1.1408x over previous
#include <cuda_runtime.h>

// Soft-DTW, gamma = 0.01, p = 2, B = 64, M = N = 512.
// One CTA per batch; 256 threads; thread jj owns columns colA=2jj, colB=2jj+1.
// R9-proven dataflow: at local step t (global s = t + 64w) thread jj computes
//   A = (iiA = t - 2*lane, colA), B = (iiA - 1, colB)
//   B deps all-register; A deps via shfl (lane>0) / write-once mailbox (lane 0).
// This revision cuts per-iteration instructions:
//   - mailbox rows padded to 640 (+64 offset); tail slots prefilled valid ->
//     ONE fused loop, no index clamps, unconditional publish
//   - ysh padded +-64/72 -> no clamp on the y prefetch
//   - shfl issued immediately after rB (latency overlapped with publish/verify)

#define BIG   1e30f
#define KEXP  144.26950408889634f    // 100 * log2(e)
#define GLN2  0.006931471805599453f  // 0.01 * ln(2)

__device__ __forceinline__ float ex2f_(float v) {
    float r; asm("ex2.approx.ftz.f32 %0, %1;" : "=f"(r) : "f"(v)); return r;
}
__device__ __forceinline__ float lg2f_(float v) {
    float r; asm("lg2.approx.ftz.f32 %0, %1;" : "=f"(r) : "f"(v)); return r;
}

// softmin3 = m - gamma*ln(1 + e^{(m-v1)/g} + e^{(m-v2)/g})  (proven numerics)
__device__ __forceinline__ float softmin3(float dg, float up, float lf) {
    float t1 = fminf(dg, up);
    float t2 = fmaxf(dg, up);
    float m  = fminf(t1, lf);
    float u  = fmaxf(t1, lf);
    float mk = m * KEXP;
    float a1 = fmaf(-KEXP, t2, mk);
    float a2 = fmaf(-KEXP, u,  mk);
    float ss = 1.0f + ex2f_(a1) + ex2f_(a2);
    return fmaf(-GLN2, lg2f_(ss), m);
}

__device__ __forceinline__ uint2 lds_v2_vol(const uint2* p) {
    uint2 r; unsigned a = (unsigned)__cvta_generic_to_shared(p);
    asm volatile("ld.volatile.shared.v2.u32 {%0,%1}, [%2];"
                 : "=r"(r.x), "=r"(r.y) : "r"(a));
    return r;
}
__device__ __forceinline__ void sts_v2_vol(uint2* p, unsigned vx, unsigned vy) {
    unsigned a = (unsigned)__cvta_generic_to_shared(p);
    asm volatile("st.volatile.shared.v2.u32 [%0], {%1,%2};"
                 :: "r"(a), "r"(vx), "r"(vy) : "memory");
}
// Verify prefetched mailbox entry {pre.x=valBits, pre.y=tag} against tag t;
// reload (rare) until the tag matches. Warp-uniform slot => uniform branches.
__device__ __forceinline__ float mb_verify(const uint2* slot, unsigned t, uint2& pre) {
    unsigned a = (unsigned)__cvta_generic_to_shared(slot);
    asm volatile("{\n\t"
        ".reg .pred p;\n\t"
        "setp.eq.u32 p, %1, %2;\n\t"
        "@p bra D%=;\n\t"
        "R%=:\n\t"
        "ld.volatile.shared.v2.u32 {%0,%1}, [%3];\n\t"
        "setp.ne.u32 p, %1, %2;\n\t"
        "@p bra R%=;\n\t"
        "D%=:\n\t"
        "}"
        : "+r"(pre.x), "+r"(pre.y) : "r"(t), "r"(a) : "memory");
    return __uint_as_float(pre.x);
}

__global__ __launch_bounds__(256, 1)
void softdtw_kernel(const float* __restrict__ x,
                    const float* __restrict__ y,
                    float* __restrict__ out)
{
    __shared__ float yshp_raw[648];  // logical rows [-64, 584); offset 64
    __shared__ uint2 bnd[8][640];    // slot k holds row k-64; rows 0..6 real, 7 dummy

    const int b    = blockIdx.x;
    const int jj   = threadIdx.x;          // 0..255
    const int w    = jj >> 5;
    const int lane = jj & 31;
    const int colA = 2 * jj;
    const int colB = colA + 1;
    float* yshp = yshp_raw + 64;

    yshp[colA] = y[b * 512 + colA];
    yshp[colB] = y[b * 512 + colB];
    const float xA = x[b * 512 + colA];
    const float xB = x[b * 512 + colB];
    if (jj < 64) yshp_raw[jj] = 0.0f;                    // bottom pad
    if (jj < 72) yshp_raw[576 + jj] = 0.0f;              // top pad

    // mailboxes: poison writable slots [0,576) of rows 0..6;
    // prefill tail slots [576,640) of rows 0..6 and ALL of dummy row 7 with
    // {BIG, tag = slot-64} (always-valid; producer's slot-576 write is identical)
    for (int s = jj; s < 7 * 576; s += 256) {
        int r = s / 576, k = s - r * 576;
        bnd[r][k].y = 0xFFFFFFFFu;
    }
    for (int s = jj; s < 7 * 64; s += 256) {
        int r = s >> 6, k = (s & 63) + 576;
        bnd[r][k] = make_uint2(__float_as_uint(BIG), (unsigned)(k - 64));
    }
    for (int t = jj; t < 640; t += 256)
        bnd[7][t] = make_uint2(__float_as_uint(BIG), (unsigned)(t - 64));
    __syncthreads();                        // the only full barrier

    const uint2* mrow = bnd[(w + 7) & 7];   // w=0 -> dummy row 7; else bnd[w-1]
    uint2*       prow = bnd[w & 7];         // producer row (used only if w<7)
    const bool   isPub = (lane == 31) && (w < 7);

    float aPrev  = BIG;                     // A(t-1)
    float aPrev2 = BIG;                     // A(t-2)
    float bPrev  = BIG;                     // B(t-1)
    float nbPrev = (jj == 0) ? 0.0f : BIG;  // neighbor B(t-2); R[-1,-1]=0 seed

    float yA = yshp[-2 * lane];             // ysh[iiA] at t=0 (pad if negative)
    float yB = yshp[-2 * lane - 1];         // ysh[iiA-1]

    uint2 pre    = lds_v2_vol(&mrow[64]);                 // slot for t=0
    float nbCurS = __shfl_up_sync(0xffffffffu, bPrev, 1); // = BIG (pre-loop shfl)

    // ---- fused main loop: t = 0..574 ----
    #pragma unroll 4
    for (int t = 0; t < 575; ++t) {
        const int iiA  = t - 2 * lane;
        const int rowB = iiA - 1;

        float nbCur = nbCurS;

        // B cell first: register-only deps
        float dB = xB - yB;
        float rB = fmaf(dB, dB, softmin3(aPrev2, bPrev, aPrev));
        rB = ((unsigned)rowB < 512u) ? rB : BIG;

        // shfl for NEXT iteration issued immediately after rB is ready
        float nbNext = __shfl_up_sync(0xffffffffu, rB, 1);

        // publish unconditionally into the padded row (slot = rowB + 64)
        if (isPub)
            sts_v2_vol(&prow[rowB + 64], __float_as_uint(rB), (unsigned)rowB);

        // mailbox value for lane 0 (uniform slot/tag across the warp)
        float mv = mb_verify(&mrow[t + 64], (unsigned)t, pre);
        if (lane == 0) nbCur = mv;

        // A cell
        float dA = xA - yA;
        float rA = fmaf(dA, dA, softmin3(nbPrev, aPrev, nbCur));
        rA = ((unsigned)iiA < 512u) ? rA : BIG;

        // rotate state
        aPrev2 = aPrev;  aPrev = rA;  bPrev = rB;
        nbPrev = nbCur;  nbCurS = nbNext;
        yB = yA;
        yA = yshp[iiA + 1];                 // padded: no clamp

        pre = lds_v2_vol(&mrow[t + 65]);    // prefetch next slot (<= 639)
    }

    if (jj == 255) out[b] = bPrev;          // rB at t=574, rowB=511 -> R[511,511]
}

extern "C" void kernel_launch(void* const* d_in, const int* in_sizes, int n_in,
                              void* d_out, int out_size)
{
    const float* x = (const float*)d_in[0];
    const float* y = (const float*)d_in[1];
    float* out = (float*)d_out;
    softdtw_kernel<<<64, 256>>>(x, y, out);
}

// round 16
// speedup vs baseline: 1.2832x; 1.0758x over previous
#include <cuda_runtime.h>

// Soft-DTW, gamma = 0.01, p = 2, B = 64, M = N = 512.
// One CTA per batch; 128 threads = 4 warps = 1 warp per SMSP.
// Lane L of warp w owns columns c0 = 128w + 4L .. c0+3 (4 cols/thread).
// At local step t (global s = t + 128w), cell k = (row t-4L-k, col c0+k).
//   cells 1..3: left/diag deps are own cell k-1 history  -> registers
//   cell 0:     left/diag from lane L-1 cell 3           -> shfl / mailbox
// Cross-warp mailbox (lane 0 of warp w>0 <- lane 31 cell 3 of warp w-1):
//   write-once slots {value, tag=row}; consumer verifies tag at t+DELTA and
//   reads value at t (producer store order makes this safe); after any spin
//   the slack self-restores to DELTA. Warp 0 reads an always-valid dummy row.

#define BIG   1e30f
#define KEXP  144.26950408889634f    // 100 * log2(e)
#define GLN2  0.006931471805599453f  // 0.01 * ln(2)
#define DELTA 16

#define NSLOT 832                    // logical slots [-128, 704), offset +128

__device__ __forceinline__ float ex2f_(float v) {
    float r; asm("ex2.approx.ftz.f32 %0, %1;" : "=f"(r) : "f"(v)); return r;
}
__device__ __forceinline__ float lg2f_(float v) {
    float r; asm("lg2.approx.ftz.f32 %0, %1;" : "=f"(r) : "f"(v)); return r;
}

// softmin3 = m - gamma*ln(1 + e^{(m-v1)/g} + e^{(m-v2)/g})  (proven numerics)
__device__ __forceinline__ float softmin3(float dg, float up, float lf) {
    float t1 = fminf(dg, up);
    float t2 = fmaxf(dg, up);
    float m  = fminf(t1, lf);
    float u  = fmaxf(t1, lf);
    float mk = m * KEXP;
    float a1 = fmaf(-KEXP, t2, mk);
    float a2 = fmaf(-KEXP, u,  mk);
    float ss = 1.0f + ex2f_(a1) + ex2f_(a2);
    return fmaf(-GLN2, lg2f_(ss), m);
}

__device__ __forceinline__ unsigned lds_u32_vol(const void* p) {
    unsigned a = (unsigned)__cvta_generic_to_shared(p); unsigned v;
    asm volatile("ld.volatile.shared.u32 %0, [%1];" : "=r"(v) : "r"(a));
    return v;
}
__device__ __forceinline__ void sts_v2_vol_addr(unsigned a, unsigned vx, unsigned vy) {
    asm volatile("st.volatile.shared.v2.u32 [%0], {%1,%2};"
                 :: "r"(a), "r"(vx), "r"(vy) : "memory");
}
// Verify preloaded tag 'cur' == want; rare spin reloads the slot's tag word.
// All operands warp-uniform -> uniform branches, no divergence.
__device__ __forceinline__ void tag_verify(unsigned cur, unsigned want, const uint2* slot) {
    unsigned a = (unsigned)__cvta_generic_to_shared(&slot->y);
    asm volatile("{\n\t"
        ".reg .pred p;\n\t"
        "setp.eq.u32 p, %0, %1;\n\t"
        "@p bra D%=;\n\t"
        "R%=:\n\t"
        "ld.volatile.shared.u32 %0, [%2];\n\t"
        "setp.ne.u32 p, %0, %1;\n\t"
        "@p bra R%=;\n\t"
        "D%=:\n\t"
        "}" : "+r"(cur) : "r"(want), "r"(a) : "memory");
}

__global__ __launch_bounds__(128, 1)
void softdtw_kernel(const float* __restrict__ x,
                    const float* __restrict__ y,
                    float* __restrict__ out)
{
    __shared__ float yshp_raw[776];        // logical rows [-128, 648), offset +128
    __shared__ uint2 bnd[4][NSLOT];        // rows 0..2 mailboxes, row 3 dummy
    __shared__ uint2 scratch[4][32];       // branch-free publish sink per warp

    const int tid  = threadIdx.x;          // 0..127
    const int b    = blockIdx.x;
    const int w    = tid >> 5;             // warp 0..3
    const int L    = tid & 31;
    const int c0   = 128 * w + 4 * L;
    float* yshp = yshp_raw + 128;

    // loads
    const float x0 = x[b * 512 + c0 + 0];
    const float x1 = x[b * 512 + c0 + 1];
    const float x2 = x[b * 512 + c0 + 2];
    const float x3 = x[b * 512 + c0 + 3];
    for (int i = tid; i < 512; i += 128) yshp[i] = y[b * 512 + i];
    for (int i = tid; i < 128; i += 128) yshp_raw[i] = 0.0f;           // low pad
    for (int i = tid; i < 136; i += 128) yshp_raw[640 + i] = 0.0f;     // high pad

    // mailboxes: poison writable slots [0,640) of rows 0..2; prefill tail
    // [640, NSLOT) of rows 0..2 and ALL of dummy row 3 with {BIG, tag=slot-128}
    for (int i = tid; i < 3 * 640; i += 128) {
        int r = i / 640, k = i - r * 640;
        bnd[r][k].y = 0xFFFFFFFFu;
    }
    for (int i = tid; i < 3 * 192; i += 128) {
        int r = i / 192, k = (i - r * 192) + 640;
        bnd[r][k] = make_uint2(__float_as_uint(BIG), (unsigned)(k - 128));
    }
    for (int k = tid; k < NSLOT; k += 128)
        bnd[3][k] = make_uint2(__float_as_uint(BIG), (unsigned)(k - 128));
    __syncthreads();                        // the only full barrier

    const uint2* mrow = &bnd[(w + 3) & 3][128];   // w=0 -> dummy row 3
    // branch-free publish address: lane31 of w<3 -> real slot, else scratch
    const bool realPub = (L == 31) && (w < 3);
    unsigned pubBase = (unsigned)__cvta_generic_to_shared(
        realPub ? (void*)&bnd[w][128] : (void*)&scratch[w][L & 31]);
    // real: addr = pubBase + rowP*8 ; scratch: addr = pubBase (fixed)
    const unsigned pubStride = realPub ? 8u : 0u;

    // state
    float rP0 = BIG, rP1 = BIG, rP2c = BIG, rP3 = BIG;     // r[k](t-1)
    float q0 = BIG, q1 = BIG, q2 = BIG;                    // r[k](t-2), k=0..2
    float nbPrev = (tid == 0) ? 0.0f : BIG;                // neighbor r3(t-2)/mv(t-1)

    // y registers: yR[k] = y[r0 - k], r0 = t - 4L
    float yR0 = yshp[-4 * L];
    float yR1 = yshp[-4 * L - 1];
    float yR2 = yshp[-4 * L - 2];
    float yR3 = yshp[-4 * L - 3];

    // prime mailbox pipeline: ensure slots <= DELTA written, then prefetch
    {
        unsigned cur = lds_u32_vol(&mrow[DELTA].y);
        tag_verify(cur, (unsigned)DELTA, &mrow[DELTA]);
    }
    float    preVal = __uint_as_float(lds_u32_vol(&mrow[0].x));
    unsigned tagPre = lds_u32_vol(&mrow[1 + DELTA].y);

    int r0 = -4 * L;                        // row of cell 0 at current t

    #pragma unroll 2
    for (int t = 0; t < 639; ++t, ++r0) {
        // neighbor current: lane L-1's r3(t-1); lane 0: mailbox slot t
        float nbCur = __shfl_up_sync(0xffffffffu, rP3, 1);
        if (L == 0) nbCur = preVal;

        // cell 0 (needs neighbor)
        float d0 = x0 - yR0;
        float n0 = fmaf(d0, d0, softmin3(nbPrev, rP0, nbCur));
        n0 = ((unsigned)r0 < 512u) ? n0 : BIG;
        // cells 1..3 (register-only deps)
        float d1 = x1 - yR1;
        float n1 = fmaf(d1, d1, softmin3(q0, rP1, rP0));
        n1 = ((unsigned)(r0 - 1) < 512u) ? n1 : BIG;
        float d2 = x2 - yR2;
        float n2 = fmaf(d2, d2, softmin3(q1, rP2c, rP1));
        n2 = ((unsigned)(r0 - 2) < 512u) ? n2 : BIG;
        float d3 = x3 - yR3;
        float n3 = fmaf(d3, d3, softmin3(q2, rP3, rP2c));
        n3 = ((unsigned)(r0 - 3) < 512u) ? n3 : BIG;

        // publish (branch-free): real slot rowP = t-127 for lane31 w<3, else scratch
        {
            int rowP = t - 127;
            unsigned addr = pubBase + (unsigned)rowP * pubStride;
            sts_v2_vol_addr(addr, __float_as_uint(n3), (unsigned)rowP);
        }

        // mailbox pipeline (off the register chain):
        // verify slack-ahead tag, then prefetch value t+1 and tag t+2+DELTA
        tag_verify(tagPre, (unsigned)(t + 1 + DELTA), &mrow[t + 1 + DELTA]);
        preVal = __uint_as_float(lds_u32_vol(&mrow[t + 1].x));
        tagPre = lds_u32_vol(&mrow[t + 2 + DELTA].y);

        // rotate state
        q0 = rP0;  q1 = rP1;  q2 = rP2c;
        rP0 = n0;  rP1 = n1;  rP2c = n2;  rP3 = n3;
        nbPrev = nbCur;
        yR3 = yR2; yR2 = yR1; yR1 = yR0;
        yR0 = yshp[r0 + 1];
    }

    // R[511,511] = cell 3 of lane 31, warp 3 at t = 638
    if (tid == 127) out[b] = rP3;
}

extern "C" void kernel_launch(void* const* d_in, const int* in_sizes, int n_in,
                              void* d_out, int out_size)
{
    const float* x = (const float*)d_in[0];
    const float* y = (const float*)d_in[1];
    float* out = (float*)d_out;
    softdtw_kernel<<<64, 128>>>(x, y, out);
}